// round 6
// baseline (speedup 1.0000x reference)
#include <cuda_runtime.h>
#include <math.h>

#define SEGS     512
#define MAXD     512
#define NTBL     7            // pos 0+1 share a map -> pre-summed into table 0
#define GUARD    16           // guard segments each side (clamp-free eval)
#define SEGT     (SEGS + 2 * GUARD)   // 544 segments per table
#define TBLC     (NTBL * SEGT)        // 3808 entries per region
#define WDIM     512
#define HDIM     512
#define BATCH    16
#define CHAN     3
#define NW       1025

#define MAGIC     12582912.0f         // 1.5 * 2^23
#define MAGICBITS 0x4B400000u         // bit pattern of 12582912.0f

// packed f32x2 constants (lo|hi identical)
#define HALF2     0x3F0000003F000000ULL
#define MAGIC2    0x4B4000004B400000ULL
#define NMAGIC2   0xCB400000CB400000ULL
#define NEG1_2    0xBF800000BF800000ULL

struct PosConsts {
    float Cx[NTBL];
    float Cy[NTBL];
    float D [NTBL];              // includes the -0.5 midpoint shift
};

// Midpoint-centered per-segment quadratics, 1/8 folded in:
//   val(v) = C + v*(B + v*A),  v = ys - k,  ys = xs - 0.5
// Guard segments (k<0 or k>=512) are exact re-centerings of segments 0/511.
// Layout per channel: [0,TBLC) = (A,B) float2; [TBLC,2*TBLC) = (C, 0)
__device__ float2 g_tab[CHAN * 2 * TBLC];

__global__ __launch_bounds__(256)
void prep_coef_kernel(const float* __restrict__ wts)
{
    int idx = blockIdx.x * 256 + threadIdx.x;           // [0, 3*7*544)
    if (idx >= CHAN * TBLC) return;
    int j   = idx % SEGT;                               // 0..543
    int ct  = idx / SEGT;
    int c   = ct / NTBL;
    int tbl = ct - c * NTBL;

    int k  = j - GUARD;                                 // segment id (may be out of range)
    int kk = k < 0 ? 0 : (k > SEGS - 1 ? SEGS - 1 : k); // clamped source segment
    double delta = (double)(k - kk);

    // base midpoint coefficients of source segment kk (double precision)
    double A, B, C;
    {
        auto coef = [&](int pos, double& a, double& b, double& cc) {
            const float* w = wts + (pos * CHAN + c) * NW + 2 * kk;
            double w0 = w[0], w1 = w[1], w2 = w[2];
            a  = 2.0 * (w0 + w2) - 4.0 * w1;
            b  = w2 - w0;
            cc = w1;
        };
        if (tbl == 0) {                                  // pos 0 + pos 1 summed
            double a0, b0, c0, a1, b1, c1;
            coef(0, a0, b0, c0);
            coef(1, a1, b1, c1);
            A = a0 + a1; B = b0 + b1; C = c0 + c1;
        } else {
            coef(tbl + 1, A, B, C);
        }
    }
    // re-center by delta: q_guard(v) = q_src(v + delta)
    double Bg = B + 2.0 * A * delta;
    double Cg = C + B * delta + A * delta * delta;

    int o = c * 2 * TBLC + tbl * SEGT + j;
    g_tab[o]        = make_float2((float)(0.125 * A), (float)(0.125 * Bg));
    g_tab[o + TBLC] = make_float2((float)(0.125 * Cg), 0.f);
}

// ---- packed f32x2 helpers ----
__device__ __forceinline__ unsigned long long fma2(unsigned long long a,
                                                   unsigned long long b,
                                                   unsigned long long c)
{
    unsigned long long d;
    asm("fma.rn.f32x2 %0, %1, %2, %3;" : "=l"(d) : "l"(a), "l"(b), "l"(c));
    return d;
}
__device__ __forceinline__ unsigned long long add2(unsigned long long a,
                                                   unsigned long long b)
{
    unsigned long long d;
    asm("add.rn.f32x2 %0, %1, %2;" : "=l"(d) : "l"(a), "l"(b));
    return d;
}
__device__ __forceinline__ unsigned long long pack2(float lo, float hi)
{
    unsigned long long d;
    asm("mov.b64 %0, {%1, %2};" : "=l"(d) : "f"(lo), "f"(hi));
    return d;
}
__device__ __forceinline__ void unpack2u(unsigned long long v, unsigned& lo, unsigned& hi)
{
    asm("mov.b64 {%0, %1}, %2;" : "=r"(lo), "=r"(hi) : "l"(v));
}

__global__ __launch_bounds__(512, 3)
void stripe_poly_kernel(const float* __restrict__ x,
                        float* __restrict__ out,
                        PosConsts pc)
{
    extern __shared__ float2 sT[];                       // 2*3808 float2 = 59.5 KB

    const int c = blockIdx.y;

    for (int k = threadIdx.x; k < 2 * TBLC; k += 512)
        sT[k] = g_tab[c * 2 * TBLC + k];
    __syncthreads();

    // each thread owns a pixel PAIR (same row, h and h+1)
    const int p0 = blockIdx.x * 1024 + threadIdx.x * 2;  // grid.x*1024 == 512*512
    const float wx = (float)(p0 >> 9);
    const float h0 = (float)(p0 & 511);
    const float h1 = h0 + 1.0f;

    unsigned long long Pp[NTBL];
#pragma unroll
    for (int i = 0; i < NTBL; i++) {
        float Pa = fmaf(pc.Cx[i], wx, fmaf(pc.Cy[i], h0, pc.D[i]));
        float Pb = fmaf(pc.Cx[i], wx, fmaf(pc.Cy[i], h1, pc.D[i]));
        Pp[i] = pack2(Pa, Pb);
    }

#pragma unroll 1
    for (int b = 0; b < BATCH; b++) {
        const int eidx = ((b * CHAN + c) << 18) + p0;
        unsigned long long xp = *(const unsigned long long*)(x + eidx); // 2 pixels
        float accU0 = 0.f, accC0 = 0.f, accU1 = 0.f, accC1 = 0.f;
#pragma unroll
        for (int i = 0; i < NTBL; i++) {
            unsigned long long ysp = fma2(HALF2, xp, Pp[i]);   // ys = 0.5*x + P
            unsigned long long gp  = add2(ysp, MAGIC2);        // RNE round
            unsigned long long sfp = add2(gp, NMAGIC2);        // float k
            unsigned long long vp  = fma2(sfp, NEG1_2, ysp);   // v = ys - k
            unsigned g0, g1;
            unpack2u(gp, g0, g1);
            const unsigned OFS = (unsigned)(i * SEGT + GUARD) - MAGICBITS;
            unsigned i0 = g0 + OFS;
            unsigned i1 = g1 + OFS;
            float2 ab0 = sT[i0];
            float2 ab1 = sT[i1];
            float  c0  = sT[i0 + TBLC].x;
            float  c1  = sT[i1 + TBLC].x;
            unsigned vu0, vu1;
            unpack2u(vp, vu0, vu1);
            float v0 = __uint_as_float(vu0);
            float v1 = __uint_as_float(vu1);
            accC0 += c0;
            accC1 += c1;
            accU0 = fmaf(v0, fmaf(v0, ab0.x, ab0.y), accU0);
            accU1 = fmaf(v1, fmaf(v1, ab1.x, ab1.y), accU1);
        }
        float2 o = make_float2(accU0 + accC0, accU1 + accC1);
        *(float2*)(out + eidx) = o;
    }
}

extern "C" void kernel_launch(void* const* d_in, const int* in_sizes, int n_in,
                              void* d_out, int out_size)
{
    const float* x   = (const float*)d_in[0];   // [16, 3, 512, 512]
    const float* wts = (const float*)d_in[1];   // [8, 3, 1025]
    float* out = (float*)d_out;

    // Fold position maps analytically (host, double precision):
    //   xs = 0.5*x + (r - rmin)*S,  S = RATIO*512/dr,  r = cx*w + sgn*cy*h
    //   D additionally absorbs the -0.5 midpoint shift (ys = xs - 0.5).
    PosConsts pc;
    const double RATIO = (double)MAXD / (double)(MAXD + 1);
    for (int rot = 0; rot < 4; rot++) {
        double theta = (M_PI / 2.0) * ((double)rot / 4.0);
        double cx = cos(theta), cy = sin(theta);
        for (int s = 0; s < 2; s++) {
            int pos = rot * 2 + s;
            int tbl = (pos <= 1) ? 0 : pos - 1;          // pos 0,1 -> table 0
            double sgn  = (s == 0) ? 1.0 : -1.0;
            double rmin = (s == 0) ? 0.0 : -cy * (HDIM - 1);
            double rmax = (s == 0) ? (cx + cy) * (WDIM - 1) : cx * (WDIM - 1);
            double dr   = rmax - rmin;
            double S    = RATIO * (double)MAXD / dr;
            pc.Cx[tbl] = (float)(cx * S);
            pc.Cy[tbl] = (float)(sgn * cy * S);
            pc.D [tbl] = (float)(-rmin * S - 0.5);
        }
    }

    prep_coef_kernel<<<(CHAN * TBLC + 255) / 256, 256>>>(wts);

    const int smem = 2 * TBLC * sizeof(float2);          // 60928 B
    cudaFuncSetAttribute(stripe_poly_kernel,
                         cudaFuncAttributeMaxDynamicSharedMemorySize, smem);
    dim3 grid(WDIM * HDIM / 1024, CHAN, 1);              // (256, 3)
    stripe_poly_kernel<<<grid, 512, smem>>>(x, out, pc);
}

// round 7
// speedup vs baseline: 1.1411x; 1.1411x over previous
#include <cuda_runtime.h>
#include <math.h>

#define SEGS     512
#define MAXD     512
#define NTBL     7            // pos 0+1 share a map -> pre-summed into table 0
#define GUARD    16           // guard segments each side (clamp-free eval)
#define SEGT     (SEGS + 2 * GUARD)   // 544 segments per table
#define TBLC     (NTBL * SEGT)        // 3808 entries per region
#define WDIM     512
#define HDIM     512
#define BATCH    16
#define CHAN     3
#define NW       1025

#define MAGIC     12582912.0f         // 1.5 * 2^23
#define MAGICBITS 0x4B400000u         // bit pattern of 12582912.0f

// packed f32x2 constants (lo|hi identical)
#define HALF2     0x3F0000003F000000ULL
#define MAGIC2    0x4B4000004B400000ULL
#define NMAGIC2   0xCB400000CB400000ULL
#define NEG1_2    0xBF800000BF800000ULL

struct PosConsts {
    float Cx[NTBL];
    float Cy[NTBL];
    float D [NTBL];              // includes the -0.5 midpoint shift
};

// Midpoint-centered per-segment quadratics, 1/8 folded in:
//   val(v) = C + v*(B + v*A),  v = ys - k,  ys = xs - 0.5
// Guard segments (k<0 or k>=512) are exact re-centerings of segments 0/511.
// SoA: (A,B) float2 array + packed C float array (4B stride -> all banks).
__device__ float2 g_AB[CHAN * TBLC];
__device__ float  g_C [CHAN * TBLC];

__global__ __launch_bounds__(256)
void prep_coef_kernel(const float* __restrict__ wts)
{
    int idx = blockIdx.x * 256 + threadIdx.x;           // [0, 3*7*544)
    if (idx >= CHAN * TBLC) return;
    int j   = idx % SEGT;                               // 0..543
    int ct  = idx / SEGT;
    int c   = ct / NTBL;
    int tbl = ct - c * NTBL;

    int k  = j - GUARD;                                 // segment id (may be out of range)
    int kk = k < 0 ? 0 : (k > SEGS - 1 ? SEGS - 1 : k); // clamped source segment
    double delta = (double)(k - kk);

    double A, B, C;
    {
        auto coef = [&](int pos, double& a, double& b, double& cc) {
            const float* w = wts + (pos * CHAN + c) * NW + 2 * kk;
            double w0 = w[0], w1 = w[1], w2 = w[2];
            a  = 2.0 * (w0 + w2) - 4.0 * w1;
            b  = w2 - w0;
            cc = w1;
        };
        if (tbl == 0) {                                  // pos 0 + pos 1 summed
            double a0, b0, c0, a1, b1, c1;
            coef(0, a0, b0, c0);
            coef(1, a1, b1, c1);
            A = a0 + a1; B = b0 + b1; C = c0 + c1;
        } else {
            coef(tbl + 1, A, B, C);
        }
    }
    // re-center by delta: q_guard(v) = q_src(v + delta)
    double Bg = B + 2.0 * A * delta;
    double Cg = C + B * delta + A * delta * delta;

    int o = c * TBLC + tbl * SEGT + j;
    g_AB[o] = make_float2((float)(0.125 * A), (float)(0.125 * Bg));
    g_C [o] = (float)(0.125 * Cg);
}

// ---- packed f32x2 helpers ----
__device__ __forceinline__ unsigned long long fma2(unsigned long long a,
                                                   unsigned long long b,
                                                   unsigned long long c)
{
    unsigned long long d;
    asm("fma.rn.f32x2 %0, %1, %2, %3;" : "=l"(d) : "l"(a), "l"(b), "l"(c));
    return d;
}
__device__ __forceinline__ unsigned long long add2(unsigned long long a,
                                                   unsigned long long b)
{
    unsigned long long d;
    asm("add.rn.f32x2 %0, %1, %2;" : "=l"(d) : "l"(a), "l"(b));
    return d;
}
__device__ __forceinline__ unsigned long long pack2(float lo, float hi)
{
    unsigned long long d;
    asm("mov.b64 %0, {%1, %2};" : "=l"(d) : "f"(lo), "f"(hi));
    return d;
}
__device__ __forceinline__ void unpack2u(unsigned long long v, unsigned& lo, unsigned& hi)
{
    asm("mov.b64 {%0, %1}, %2;" : "=r"(lo), "=r"(hi) : "l"(v));
}

__global__ __launch_bounds__(512, 3)
void stripe_poly_kernel(const float* __restrict__ x,
                        float* __restrict__ out,
                        PosConsts pc)
{
    __shared__ float2 sAB[TBLC];                         // 30464 B
    __shared__ float  sC [TBLC];                         // 15232 B

    const int c = blockIdx.y;

    for (int k = threadIdx.x; k < TBLC; k += 512) {
        int o = c * TBLC + k;
        sAB[k] = g_AB[o];
        sC [k] = g_C [o];
    }
    __syncthreads();

    // each thread owns a pixel PAIR (same row, h and h+1)
    const int p0 = blockIdx.x * 1024 + threadIdx.x * 2;  // grid.x*1024 == 512*512
    const float wx = (float)(p0 >> 9);
    const float h0 = (float)(p0 & 511);
    const float h1 = h0 + 1.0f;

    unsigned long long Pp[NTBL];
#pragma unroll
    for (int i = 0; i < NTBL; i++) {
        float Pa = fmaf(pc.Cx[i], wx, fmaf(pc.Cy[i], h0, pc.D[i]));
        float Pb = fmaf(pc.Cx[i], wx, fmaf(pc.Cy[i], h1, pc.D[i]));
        Pp[i] = pack2(Pa, Pb);
    }

#pragma unroll 1
    for (int b = 0; b < BATCH; b++) {
        const int eidx = ((b * CHAN + c) << 18) + p0;
        unsigned long long xp = *(const unsigned long long*)(x + eidx); // 2 pixels
        float accU0 = 0.f, accC0 = 0.f, accU1 = 0.f, accC1 = 0.f;
#pragma unroll
        for (int i = 0; i < NTBL; i++) {
            unsigned long long ysp = fma2(HALF2, xp, Pp[i]);   // ys = 0.5*x + P
            unsigned long long gp  = add2(ysp, MAGIC2);        // RNE round -> float k
            unsigned long long sfp = add2(gp, NMAGIC2);        // exact float k
            unsigned long long vp  = fma2(sfp, NEG1_2, ysp);   // v = ys - k
            unsigned g0, g1;
            unpack2u(gp, g0, g1);
            const unsigned OFS = (unsigned)(i * SEGT + GUARD) - MAGICBITS;
            unsigned i0 = g0 + OFS;                            // wraps to table idx
            unsigned i1 = g1 + OFS;
            float2 ab0 = sAB[i0];
            float2 ab1 = sAB[i1];
            float  c0  = sC [i0];
            float  c1  = sC [i1];
            unsigned vu0, vu1;
            unpack2u(vp, vu0, vu1);
            float v0 = __uint_as_float(vu0);
            float v1 = __uint_as_float(vu1);
            accC0 += c0;
            accC1 += c1;
            accU0 = fmaf(v0, fmaf(v0, ab0.x, ab0.y), accU0);
            accU1 = fmaf(v1, fmaf(v1, ab1.x, ab1.y), accU1);
        }
        float2 o = make_float2(accU0 + accC0, accU1 + accC1);
        *(float2*)(out + eidx) = o;
    }
}

extern "C" void kernel_launch(void* const* d_in, const int* in_sizes, int n_in,
                              void* d_out, int out_size)
{
    const float* x   = (const float*)d_in[0];   // [16, 3, 512, 512]
    const float* wts = (const float*)d_in[1];   // [8, 3, 1025]
    float* out = (float*)d_out;

    // Fold position maps analytically (host, double precision):
    //   xs = 0.5*x + (r - rmin)*S,  S = RATIO*512/dr,  r = cx*w + sgn*cy*h
    //   D additionally absorbs the -0.5 midpoint shift (ys = xs - 0.5).
    PosConsts pc;
    const double RATIO = (double)MAXD / (double)(MAXD + 1);
    for (int rot = 0; rot < 4; rot++) {
        double theta = (M_PI / 2.0) * ((double)rot / 4.0);
        double cx = cos(theta), cy = sin(theta);
        for (int s = 0; s < 2; s++) {
            int pos = rot * 2 + s;
            int tbl = (pos <= 1) ? 0 : pos - 1;          // pos 0,1 -> table 0
            double sgn  = (s == 0) ? 1.0 : -1.0;
            double rmin = (s == 0) ? 0.0 : -cy * (HDIM - 1);
            double rmax = (s == 0) ? (cx + cy) * (WDIM - 1) : cx * (WDIM - 1);
            double dr   = rmax - rmin;
            double S    = RATIO * (double)MAXD / dr;
            pc.Cx[tbl] = (float)(cx * S);
            pc.Cy[tbl] = (float)(sgn * cy * S);
            pc.D [tbl] = (float)(-rmin * S - 0.5);
        }
    }

    prep_coef_kernel<<<(CHAN * TBLC + 255) / 256, 256>>>(wts);

    dim3 grid(WDIM * HDIM / 1024, CHAN, 1);              // (256, 3)
    stripe_poly_kernel<<<grid, 512>>>(x, out, pc);
}

// round 8
// speedup vs baseline: 1.3498x; 1.1829x over previous
#include <cuda_runtime.h>
#include <math.h>

#define SEGS     512
#define MAXD     512
#define NTBL     7            // pos 0+1 share a map -> pre-summed into table 0
#define GUARD    16           // guard segments each side (clamp-free eval)
#define SEGT     (SEGS + 2 * GUARD)   // 544 segments per table
#define TBLC     (NTBL * SEGT)        // 3808 entries per region
#define WDIM     512
#define HDIM     512
#define BATCH    16
#define CHAN     3
#define NW       1025

#define MAGIC     12582912.0f         // 1.5 * 2^23
#define MAGICBITS 0x4B400000u         // bit pattern of 12582912.0f

// packed f32x2 constants (lo|hi identical)
#define HALF2     0x3F0000003F000000ULL
#define MAGIC2    0x4B4000004B400000ULL
#define NMAGIC2   0xCB400000CB400000ULL
#define NEG1_2    0xBF800000BF800000ULL

struct PosConsts {
    float Cx[NTBL];
    float Cy[NTBL];
    float D [NTBL];              // includes the -0.5 midpoint shift
};

// Midpoint-centered per-segment quadratics, 1/8 folded in:
//   val(v) = C + v*(B + v*A),  v = ys - k,  ys = xs - 0.5
// Guard segments (k<0 or k>=512) are exact re-centerings of segments 0/511.
// SoA: (A,B) float2 array + packed C float array (4B stride -> all banks).
__device__ float2 g_AB[CHAN * TBLC];
__device__ float  g_C [CHAN * TBLC];

__global__ __launch_bounds__(256)
void prep_coef_kernel(const float* __restrict__ wts)
{
    int idx = blockIdx.x * 256 + threadIdx.x;           // [0, 3*7*544)
    if (idx >= CHAN * TBLC) return;
    int j   = idx % SEGT;                               // 0..543
    int ct  = idx / SEGT;
    int c   = ct / NTBL;
    int tbl = ct - c * NTBL;

    int k  = j - GUARD;                                 // segment id (may be out of range)
    int kk = k < 0 ? 0 : (k > SEGS - 1 ? SEGS - 1 : k); // clamped source segment
    double delta = (double)(k - kk);

    double A, B, C;
    {
        auto coef = [&](int pos, double& a, double& b, double& cc) {
            const float* w = wts + (pos * CHAN + c) * NW + 2 * kk;
            double w0 = w[0], w1 = w[1], w2 = w[2];
            a  = 2.0 * (w0 + w2) - 4.0 * w1;
            b  = w2 - w0;
            cc = w1;
        };
        if (tbl == 0) {                                  // pos 0 + pos 1 summed
            double a0, b0, c0, a1, b1, c1;
            coef(0, a0, b0, c0);
            coef(1, a1, b1, c1);
            A = a0 + a1; B = b0 + b1; C = c0 + c1;
        } else {
            coef(tbl + 1, A, B, C);
        }
    }
    // re-center by delta: q_guard(v) = q_src(v + delta)
    double Bg = B + 2.0 * A * delta;
    double Cg = C + B * delta + A * delta * delta;

    int o = c * TBLC + tbl * SEGT + j;
    g_AB[o] = make_float2((float)(0.125 * A), (float)(0.125 * Bg));
    g_C [o] = (float)(0.125 * Cg);
}

// ---- packed f32x2 helpers ----
__device__ __forceinline__ unsigned long long fma2(unsigned long long a,
                                                   unsigned long long b,
                                                   unsigned long long c)
{
    unsigned long long d;
    asm("fma.rn.f32x2 %0, %1, %2, %3;" : "=l"(d) : "l"(a), "l"(b), "l"(c));
    return d;
}
__device__ __forceinline__ unsigned long long add2(unsigned long long a,
                                                   unsigned long long b)
{
    unsigned long long d;
    asm("add.rn.f32x2 %0, %1, %2;" : "=l"(d) : "l"(a), "l"(b));
    return d;
}
__device__ __forceinline__ unsigned long long pack2(float lo, float hi)
{
    unsigned long long d;
    asm("mov.b64 %0, {%1, %2};" : "=l"(d) : "f"(lo), "f"(hi));
    return d;
}
__device__ __forceinline__ void unpack2u(unsigned long long v, unsigned& lo, unsigned& hi)
{
    asm("mov.b64 {%0, %1}, %2;" : "=r"(lo), "=r"(hi) : "l"(v));
}

__global__ __launch_bounds__(512, 3)
void stripe_poly_kernel(const float* __restrict__ x,
                        float* __restrict__ out,
                        PosConsts pc)
{
    __shared__ float2 sAB[TBLC];                         // 30464 B
    __shared__ float  sC [TBLC];                         // 15232 B

    const int c = blockIdx.y;

    for (int k = threadIdx.x; k < TBLC; k += 512) {
        int o = c * TBLC + k;
        sAB[k] = g_AB[o];
        sC [k] = g_C [o];
    }
    __syncthreads();

    // thread owns ONE pixel (adjacent lanes = adjacent h -> conflict-free
    // gather footprint), processes batches in PAIRS via packed f32x2 math.
    const int pixel = blockIdx.x * 512 + threadIdx.x;    // grid.x*512 == 512*512
    const float wx = (float)(pixel >> 9);
    const float hy = (float)(pixel & 511);

    float P[NTBL];
#pragma unroll
    for (int i = 0; i < NTBL; i++)
        P[i] = fmaf(pc.Cx[i], wx, fmaf(pc.Cy[i], hy, pc.D[i]));

#pragma unroll 1
    for (int bp = 0; bp < BATCH / 2; bp++) {
        const int e0 = (((2 * bp)     * CHAN + c) << 18) + pixel;
        const int e1 = (((2 * bp + 1) * CHAN + c) << 18) + pixel;
        unsigned long long xp = pack2(x[e0], x[e1]);     // two batch samples
        float accU0 = 0.f, accC0 = 0.f, accU1 = 0.f, accC1 = 0.f;
#pragma unroll
        for (int i = 0; i < NTBL; i++) {
            unsigned long long PP  = pack2(P[i], P[i]);
            unsigned long long ysp = fma2(HALF2, xp, PP);      // ys = 0.5*x + P
            unsigned long long gp  = add2(ysp, MAGIC2);        // RNE round -> float k
            unsigned long long sfp = add2(gp, NMAGIC2);        // exact float k
            unsigned long long vp  = fma2(sfp, NEG1_2, ysp);   // v = ys - k
            unsigned g0, g1;
            unpack2u(gp, g0, g1);
            const unsigned OFS = (unsigned)(i * SEGT + GUARD) - MAGICBITS;
            unsigned i0 = g0 + OFS;                            // wraps to table idx
            unsigned i1 = g1 + OFS;
            float2 ab0 = sAB[i0];
            float2 ab1 = sAB[i1];
            float  c0  = sC [i0];
            float  c1  = sC [i1];
            unsigned vu0, vu1;
            unpack2u(vp, vu0, vu1);
            float v0 = __uint_as_float(vu0);
            float v1 = __uint_as_float(vu1);
            accC0 += c0;
            accC1 += c1;
            accU0 = fmaf(v0, fmaf(v0, ab0.x, ab0.y), accU0);
            accU1 = fmaf(v1, fmaf(v1, ab1.x, ab1.y), accU1);
        }
        out[e0] = accU0 + accC0;
        out[e1] = accU1 + accC1;
    }
}

extern "C" void kernel_launch(void* const* d_in, const int* in_sizes, int n_in,
                              void* d_out, int out_size)
{
    const float* x   = (const float*)d_in[0];   // [16, 3, 512, 512]
    const float* wts = (const float*)d_in[1];   // [8, 3, 1025]
    float* out = (float*)d_out;

    // Fold position maps analytically (host, double precision):
    //   xs = 0.5*x + (r - rmin)*S,  S = RATIO*512/dr,  r = cx*w + sgn*cy*h
    //   D additionally absorbs the -0.5 midpoint shift (ys = xs - 0.5).
    PosConsts pc;
    const double RATIO = (double)MAXD / (double)(MAXD + 1);
    for (int rot = 0; rot < 4; rot++) {
        double theta = (M_PI / 2.0) * ((double)rot / 4.0);
        double cx = cos(theta), cy = sin(theta);
        for (int s = 0; s < 2; s++) {
            int pos = rot * 2 + s;
            int tbl = (pos <= 1) ? 0 : pos - 1;          // pos 0,1 -> table 0
            double sgn  = (s == 0) ? 1.0 : -1.0;
            double rmin = (s == 0) ? 0.0 : -cy * (HDIM - 1);
            double rmax = (s == 0) ? (cx + cy) * (WDIM - 1) : cx * (WDIM - 1);
            double dr   = rmax - rmin;
            double S    = RATIO * (double)MAXD / dr;
            pc.Cx[tbl] = (float)(cx * S);
            pc.Cy[tbl] = (float)(sgn * cy * S);
            pc.D [tbl] = (float)(-rmin * S - 0.5);
        }
    }

    prep_coef_kernel<<<(CHAN * TBLC + 255) / 256, 256>>>(wts);

    dim3 grid(WDIM * HDIM / 512, CHAN, 1);               // (512, 3)
    stripe_poly_kernel<<<grid, 512>>>(x, out, pc);
}